// round 4
// baseline (speedup 1.0000x reference)
#include <cuda_runtime.h>
#include <cuda_bf16.h>
#include <cuda_fp16.h>
#include <cstdint>
#include <math.h>

#define N_NODES 100000
#define N_EDGES 1600000
#define IN_C 128
#define HID_C 128
#define OUT_C 64
#define SCAN_BLOCKS 256

// ---------------- scratch (static device globals; no allocation) ----------------
__device__ int   g_deg[N_NODES];
__device__ float g_dinv[N_NODES];
__device__ int   g_rowptr[N_NODES + 1];
__device__ int   g_cursor[N_NODES];
__device__ int   g_col[N_EDGES];
__device__ float g_wgt[N_EDGES];
__device__ int   g_blocksums[SCAN_BLOCKS];
__device__ __align__(16) __half g_h1h[(size_t)N_NODES * HID_C];   // fp16 hidden (layer-1 pre-agg)
__device__ __align__(16) float  g_a1[(size_t)N_NODES * HID_C];
__device__ __align__(16) float  g_h2[(size_t)N_NODES * OUT_C];
// hi/lo bf16 weights in B-operand orientation: Bs[n][k] = W[k][n]
__device__ __align__(16) __nv_bfloat16 g_w1hi[128 * 128];
__device__ __align__(16) __nv_bfloat16 g_w1lo[128 * 128];
__device__ __align__(16) __nv_bfloat16 g_w2hi[64 * 128];
__device__ __align__(16) __nv_bfloat16 g_w2lo[64 * 128];

// ---------------- degree / scan / CSR ----------------
__global__ void k_init_deg() {
    int i = blockIdx.x * 256 + threadIdx.x;
    if (i < N_NODES) g_deg[i] = 1;
}
__global__ void k_count(const int* __restrict__ dst) {
    int e = blockIdx.x * 256 + threadIdx.x;
    if (e < N_EDGES) atomicAdd(&g_deg[dst[e]], 1);
}
__global__ void k_scan_part() {
    __shared__ int wsum[16];
    int tid = threadIdx.x;
    int lane = tid & 31, wid = tid >> 5;
    int i = blockIdx.x * 512 + tid;
    int c = 0;
    if (i < N_NODES) {
        int d = g_deg[i];
        g_dinv[i] = rsqrtf((float)d);
        c = d - 1;
    }
    int v = c;
    #pragma unroll
    for (int o = 1; o < 32; o <<= 1) {
        int t = __shfl_up_sync(0xffffffffu, v, o);
        if (lane >= o) v += t;
    }
    if (lane == 31) wsum[wid] = v;
    __syncthreads();
    if (wid == 0) {
        int s = (lane < 16) ? wsum[lane] : 0;
        #pragma unroll
        for (int o = 1; o < 16; o <<= 1) {
            int t = __shfl_up_sync(0xffffffffu, s, o);
            if (lane >= o) s += t;
        }
        if (lane < 16) wsum[lane] = s;
    }
    __syncthreads();
    int off = (wid > 0) ? wsum[wid - 1] : 0;
    if (i < N_NODES) g_rowptr[i] = off + v - c;
    if (tid == 511) g_blocksums[blockIdx.x] = wsum[15];
}
__global__ void k_scan_top() {
    __shared__ int wsum[8];
    int tid = threadIdx.x;
    int lane = tid & 31, wid = tid >> 5;
    int v0 = g_blocksums[tid];
    int v = v0;
    #pragma unroll
    for (int o = 1; o < 32; o <<= 1) {
        int t = __shfl_up_sync(0xffffffffu, v, o);
        if (lane >= o) v += t;
    }
    if (lane == 31) wsum[wid] = v;
    __syncthreads();
    if (wid == 0) {
        int s = (lane < 8) ? wsum[lane] : 0;
        #pragma unroll
        for (int o = 1; o < 8; o <<= 1) {
            int t = __shfl_up_sync(0xffffffffu, s, o);
            if (lane >= o) s += t;
        }
        if (lane < 8) wsum[lane] = s;
    }
    __syncthreads();
    int off = (wid > 0) ? wsum[wid - 1] : 0;
    g_blocksums[tid] = off + v - v0;
}
__global__ void k_scan_add() {
    int i = blockIdx.x * 256 + threadIdx.x;
    if (i < N_NODES) {
        int r = g_rowptr[i] + g_blocksums[i >> 9];
        g_rowptr[i] = r;
        g_cursor[i] = r;
    }
    if (i == N_NODES) g_rowptr[N_NODES] = N_EDGES;
}
__global__ void k_fill(const int* __restrict__ src, const int* __restrict__ dst) {
    int e = blockIdx.x * 256 + threadIdx.x;
    if (e < N_EDGES) {
        int s = src[e];
        int d = dst[e];
        int pos = atomicAdd(&g_cursor[d], 1);
        g_col[pos] = s;
        g_wgt[pos] = g_dinv[s];
    }
}

// ---------------- prep: split W into bf16 hi/lo, [n][k] orientation ----------------
__global__ void k_prep_w(const float* __restrict__ W1, const float* __restrict__ W2) {
    int i = blockIdx.x * 256 + threadIdx.x;
    if (i < 128 * 128) {
        int k = i >> 7, n = i & 127;
        float v = W1[i];
        __nv_bfloat16 h = __float2bfloat16(v);
        __nv_bfloat16 l = __float2bfloat16(v - __bfloat162float(h));
        g_w1hi[n * 128 + k] = h;
        g_w1lo[n * 128 + k] = l;
    } else if (i < 128 * 128 + 64 * 128) {
        int j = i - 128 * 128;
        int k = j >> 6, n = j & 63;
        float v = W2[j];
        __nv_bfloat16 h = __float2bfloat16(v);
        __nv_bfloat16 l = __float2bfloat16(v - __bfloat162float(h));
        g_w2hi[n * 128 + k] = h;
        g_w2lo[n * 128 + k] = l;
    }
}

// ---------------- bf16 mma.sync helper ----------------
__device__ __forceinline__ void mma_bf16(float& d0, float& d1, float& d2, float& d3,
                                         uint32_t a0, uint32_t a1, uint32_t a2, uint32_t a3,
                                         uint32_t b0, uint32_t b1) {
    asm volatile(
        "mma.sync.aligned.m16n8k16.row.col.f32.bf16.bf16.f32 "
        "{%0,%1,%2,%3}, {%4,%5,%6,%7}, {%8,%9}, {%0,%1,%2,%3};"
        : "+f"(d0), "+f"(d1), "+f"(d2), "+f"(d3)
        : "r"(a0), "r"(a1), "r"(a2), "r"(a3), "r"(b0), "r"(b1));
}

__device__ __forceinline__ uint32_t pack_hi2(float x, float y) {
    __nv_bfloat162 t = __halves2bfloat162(__float2bfloat16(x), __float2bfloat16(y));
    return *(uint32_t*)&t;
}
__device__ __forceinline__ uint32_t pack_lo2(float x, float y) {
    __nv_bfloat16 hx = __float2bfloat16(x), hy = __float2bfloat16(y);
    __nv_bfloat162 t = __halves2bfloat162(__float2bfloat16(x - __bfloat162float(hx)),
                                          __float2bfloat16(y - __bfloat162float(hy)));
    return *(uint32_t*)&t;
}

// ---------------- tensor-core GEMM via mma.sync: O = A @ W (M tile=128, K=128) ----------------
template<int NOUT>
__global__ __launch_bounds__(256) void k_mma_gemm(const float* __restrict__ Ain) {
    extern __shared__ uint32_t smu[];
    constexpr int STR = 68;
    constexpr int WMG = (NOUT == 128) ? 2 : 4;
    constexpr int TM  = 128 / WMG;
    constexpr int MT  = TM / 16;
    constexpr int NT  = 4;

    uint32_t* As_hi = smu;
    uint32_t* As_lo = As_hi + 128 * STR;
    uint32_t* Bs_hi = As_lo + 128 * STR;
    uint32_t* Bs_lo = Bs_hi + NOUT * STR;

    const int tid = threadIdx.x;
    const int wid = tid >> 5;
    const int lane = tid & 31;
    const int g = lane >> 2;
    const int tg = lane & 3;
    const int row0 = blockIdx.x * 128;

    const float* Asrc = (NOUT == 128) ? Ain : g_a1;
    const uint32_t* WhG = (NOUT == 128) ? (const uint32_t*)g_w1hi : (const uint32_t*)g_w2hi;
    const uint32_t* WlG = (NOUT == 128) ? (const uint32_t*)g_w1lo : (const uint32_t*)g_w2lo;

    const float4* A4 = (const float4*)Asrc;
    #pragma unroll 4
    for (int t = 0; t < 16; t++) {
        int i = t * 256 + tid;
        int row = i >> 5, c4 = i & 31;
        int gr = row0 + row;
        float4 v = make_float4(0.f, 0.f, 0.f, 0.f);
        if (gr < N_NODES) v = A4[(size_t)gr * 32 + c4];
        uint32_t h01 = pack_hi2(v.x, v.y), h23 = pack_hi2(v.z, v.w);
        uint32_t l01 = pack_lo2(v.x, v.y), l23 = pack_lo2(v.z, v.w);
        *(uint2*)&As_hi[row * STR + c4 * 2] = make_uint2(h01, h23);
        *(uint2*)&As_lo[row * STR + c4 * 2] = make_uint2(l01, l23);
    }
    for (int i = tid; i < NOUT * 64; i += 256) {
        int n = i >> 6, kp = i & 63;
        Bs_hi[n * STR + kp] = WhG[i];
        Bs_lo[n * STR + kp] = WlG[i];
    }
    __syncthreads();

    const int wm = (NOUT == 128) ? (wid & 1) : (wid & 3);
    const int wn = (NOUT == 128) ? (wid >> 1) : (wid >> 2);

    float d[MT][NT][4];
    #pragma unroll
    for (int mt = 0; mt < MT; mt++)
        #pragma unroll
        for (int nt = 0; nt < NT; nt++)
            #pragma unroll
            for (int j = 0; j < 4; j++) d[mt][nt][j] = 0.f;

    const uint32_t* Aterm[3] = {As_hi, As_hi, As_lo};
    const uint32_t* Bterm[3] = {Bs_hi, Bs_lo, Bs_hi};

    #pragma unroll
    for (int term = 0; term < 3; term++) {
        const uint32_t* Ab = Aterm[term] + (wm * TM + g) * STR;
        const uint32_t* Bb = Bterm[term] + (wn * 32 + g) * STR;
        #pragma unroll
        for (int ks = 0; ks < 8; ks++) {
            int ko = ks * 8 + tg;
            uint32_t a[MT][4], b[NT][2];
            #pragma unroll
            for (int mt = 0; mt < MT; mt++) {
                const uint32_t* Ar = Ab + mt * 16 * STR;
                a[mt][0] = Ar[ko];
                a[mt][1] = Ar[8 * STR + ko];
                a[mt][2] = Ar[ko + 4];
                a[mt][3] = Ar[8 * STR + ko + 4];
            }
            #pragma unroll
            for (int nt = 0; nt < NT; nt++) {
                const uint32_t* Br = Bb + nt * 8 * STR;
                b[nt][0] = Br[ko];
                b[nt][1] = Br[ko + 4];
            }
            #pragma unroll
            for (int mt = 0; mt < MT; mt++)
                #pragma unroll
                for (int nt = 0; nt < NT; nt++)
                    mma_bf16(d[mt][nt][0], d[mt][nt][1], d[mt][nt][2], d[mt][nt][3],
                             a[mt][0], a[mt][1], a[mt][2], a[mt][3],
                             b[nt][0], b[nt][1]);
        }
    }

    #pragma unroll
    for (int mt = 0; mt < MT; mt++) {
        int r0 = row0 + wm * TM + mt * 16 + g;
        #pragma unroll
        for (int nt = 0; nt < NT; nt++) {
            int c = wn * 32 + nt * 8 + tg * 2;
            if (NOUT == 128) {
                // layer 1 output -> fp16
                if (r0 < N_NODES)
                    *(__half2*)&g_h1h[(size_t)r0 * 128 + c] =
                        __floats2half2_rn(d[mt][nt][0], d[mt][nt][1]);
                if (r0 + 8 < N_NODES)
                    *(__half2*)&g_h1h[(size_t)(r0 + 8) * 128 + c] =
                        __floats2half2_rn(d[mt][nt][2], d[mt][nt][3]);
            } else {
                if (r0 < N_NODES)
                    *(float2*)&g_h2[(size_t)r0 * 64 + c] = make_float2(d[mt][nt][0], d[mt][nt][1]);
                if (r0 + 8 < N_NODES)
                    *(float2*)&g_h2[(size_t)(r0 + 8) * 64 + c] = make_float2(d[mt][nt][2], d[mt][nt][3]);
            }
        }
    }
}

// ---------------- aggregate layer 1 (fp16 gathers) + bias + relu ----------------
__device__ __forceinline__ void fma_h4(float4& acc, float w, uint2 rv) {
    float2 f0 = __half22float2(*(__half2*)&rv.x);
    float2 f1 = __half22float2(*(__half2*)&rv.y);
    acc.x = fmaf(w, f0.x, acc.x);
    acc.y = fmaf(w, f0.y, acc.y);
    acc.z = fmaf(w, f1.x, acc.z);
    acc.w = fmaf(w, f1.y, acc.w);
}

__global__ __launch_bounds__(256) void k_agg1(const float* __restrict__ b1) {
    int node = blockIdx.x * 8 + (threadIdx.x >> 5);
    if (node >= N_NODES) return;
    int lane = threadIdx.x & 31;
    float di = g_dinv[node];
    const uint2* H = (const uint2*)g_h1h;   // row = 32 uint2 (128 halves)
    uint2 sv = __ldg(&H[(size_t)node * 32 + lane]);
    float4 acc = make_float4(0.f, 0.f, 0.f, 0.f);
    fma_h4(acc, di, sv);
    int beg = g_rowptr[node];
    int end = g_rowptr[node + 1];
    for (int base = beg; base < end; base += 32) {
        int lim = end - base;
        int myS = 0; float myW = 0.f;
        if (lane < lim) {
            myS = __ldg(&g_col[base + lane]);
            myW = __ldg(&g_wgt[base + lane]);
        }
        int n = lim < 32 ? lim : 32;
        #pragma unroll 4
        for (int j = 0; j < n; j++) {
            int s   = __shfl_sync(0xffffffffu, myS, j);
            float w = __shfl_sync(0xffffffffu, myW, j);
            uint2 hv = __ldg(&H[(size_t)s * 32 + lane]);
            fma_h4(acc, w, hv);
        }
    }
    float4 bv = ((const float4*)b1)[lane];
    float4 out;
    out.x = fmaxf(fmaf(acc.x, di, bv.x), 0.f);
    out.y = fmaxf(fmaf(acc.y, di, bv.y), 0.f);
    out.z = fmaxf(fmaf(acc.z, di, bv.z), 0.f);
    out.w = fmaxf(fmaf(acc.w, di, bv.w), 0.f);
    ((float4*)g_a1)[(size_t)node * 32 + lane] = out;
}

// ---------------- aggregate layer 2 + bias + log_softmax ----------------
__global__ __launch_bounds__(256) void k_agg2(const float* __restrict__ b2,
                                              float* __restrict__ out) {
    int node = blockIdx.x * 8 + (threadIdx.x >> 5);
    if (node >= N_NODES) return;
    int lane = threadIdx.x & 31;
    float di = g_dinv[node];
    const float2* H = (const float2*)g_h2;
    float2 self = __ldg(&H[(size_t)node * 32 + lane]);
    float2 acc = make_float2(di * self.x, di * self.y);
    int beg = g_rowptr[node];
    int end = g_rowptr[node + 1];
    for (int base = beg; base < end; base += 32) {
        int lim = end - base;
        int myS = 0; float myW = 0.f;
        if (lane < lim) {
            myS = __ldg(&g_col[base + lane]);
            myW = __ldg(&g_wgt[base + lane]);
        }
        int n = lim < 32 ? lim : 32;
        #pragma unroll 4
        for (int j = 0; j < n; j++) {
            int s   = __shfl_sync(0xffffffffu, myS, j);
            float w = __shfl_sync(0xffffffffu, myW, j);
            float2 hv = __ldg(&H[(size_t)s * 32 + lane]);
            acc.x = fmaf(w, hv.x, acc.x);
            acc.y = fmaf(w, hv.y, acc.y);
        }
    }
    float2 bv = ((const float2*)b2)[lane];
    float vx = fmaf(acc.x, di, bv.x);
    float vy = fmaf(acc.y, di, bv.y);

    float m = fmaxf(vx, vy);
    #pragma unroll
    for (int o = 16; o > 0; o >>= 1) m = fmaxf(m, __shfl_xor_sync(0xffffffffu, m, o));
    float s = expf(vx - m) + expf(vy - m);
    #pragma unroll
    for (int o = 16; o > 0; o >>= 1) s += __shfl_xor_sync(0xffffffffu, s, o);
    float lse = m + logf(s);
    ((float2*)out)[(size_t)node * 32 + lane] = make_float2(vx - lse, vy - lse);
}

// ---------------- launch ----------------
extern "C" void kernel_launch(void* const* d_in, const int* in_sizes, int n_in,
                              void* d_out, int out_size) {
    const float* x  = (const float*)d_in[0];
    const int*   ei = (const int*)d_in[1];
    const float* W1 = (const float*)d_in[2];
    const float* b1 = (const float*)d_in[3];
    const float* W2 = (const float*)d_in[4];
    const float* b2 = (const float*)d_in[5];
    float* out = (float*)d_out;

    const int* src = ei;
    const int* dst = ei + N_EDGES;

    const int SMEM1 = (2 * 128 * 68 + 2 * 128 * 68) * 4;  // 139264
    const int SMEM2 = (2 * 128 * 68 + 2 * 64 * 68) * 4;   // 104448
    cudaFuncSetAttribute(k_mma_gemm<128>, cudaFuncAttributeMaxDynamicSharedMemorySize, SMEM1);
    cudaFuncSetAttribute(k_mma_gemm<64>,  cudaFuncAttributeMaxDynamicSharedMemorySize, SMEM2);

    k_prep_w<<<(128 * 128 + 64 * 128 + 255) / 256, 256>>>(W1, W2);

    k_init_deg<<<(N_NODES + 255) / 256, 256>>>();
    k_count<<<(N_EDGES + 255) / 256, 256>>>(dst);
    k_scan_part<<<SCAN_BLOCKS, 512>>>();
    k_scan_top<<<1, 256>>>();
    k_scan_add<<<(N_NODES + 256) / 256, 256>>>();
    k_fill<<<(N_EDGES + 255) / 256, 256>>>(src, dst);

    const int NTILES = (N_NODES + 127) / 128;  // 782
    k_mma_gemm<128><<<NTILES, 256, SMEM1>>>(x);
    k_agg1<<<(N_NODES + 7) / 8, 256>>>(b1);
    k_mma_gemm<64><<<NTILES, 256, SMEM2>>>(nullptr);
    k_agg2<<<(N_NODES + 7) / 8, 256>>>(b2, out);
}

// round 5
// speedup vs baseline: 1.0892x; 1.0892x over previous
#include <cuda_runtime.h>
#include <cuda_bf16.h>
#include <cuda_fp16.h>
#include <cstdint>
#include <math.h>

#define N_NODES 100000
#define N_EDGES 1600000
#define IN_C 128
#define HID_C 128
#define OUT_C 64
#define SCAN_BLOCKS 256

// ---------------- scratch (static device globals; no allocation) ----------------
__device__ int   g_deg[N_NODES];          // in-degree (memset to 0 each call)
__device__ float g_dinv[N_NODES];
__device__ int   g_rowptr[N_NODES + 1];
__device__ int   g_cursor[N_NODES];
__device__ int   g_col[N_EDGES];
__device__ float g_wgt[N_EDGES];
__device__ int   g_blocksums[SCAN_BLOCKS];
__device__ __align__(16) __half g_h1h[(size_t)N_NODES * HID_C];
__device__ __align__(16) float  g_a1[(size_t)N_NODES * HID_C];
__device__ __align__(16) float  g_h2[(size_t)N_NODES * OUT_C];
__device__ __align__(16) __nv_bfloat16 g_w1hi[128 * 128];
__device__ __align__(16) __nv_bfloat16 g_w1lo[128 * 128];
__device__ __align__(16) __nv_bfloat16 g_w2hi[64 * 128];
__device__ __align__(16) __nv_bfloat16 g_w2lo[64 * 128];

// ---------------- degree / scan / CSR ----------------
__global__ void k_count(const int4* __restrict__ dst4) {
    int i = blockIdx.x * 256 + threadIdx.x;
    if (i < N_EDGES / 4) {
        int4 d = __ldg(&dst4[i]);
        atomicAdd(&g_deg[d.x], 1);
        atomicAdd(&g_deg[d.y], 1);
        atomicAdd(&g_deg[d.z], 1);
        atomicAdd(&g_deg[d.w], 1);
    }
}

__global__ void k_scan_part() {
    __shared__ int wsum[16];
    int tid = threadIdx.x;
    int lane = tid & 31, wid = tid >> 5;
    int i = blockIdx.x * 512 + tid;
    int c = 0;
    if (i < N_NODES) {
        int d = g_deg[i];                 // in-degree
        g_dinv[i] = rsqrtf((float)(d + 1));  // +1 self-loop
        c = d;
    }
    int v = c;
    #pragma unroll
    for (int o = 1; o < 32; o <<= 1) {
        int t = __shfl_up_sync(0xffffffffu, v, o);
        if (lane >= o) v += t;
    }
    if (lane == 31) wsum[wid] = v;
    __syncthreads();
    if (wid == 0) {
        int s = (lane < 16) ? wsum[lane] : 0;
        #pragma unroll
        for (int o = 1; o < 16; o <<= 1) {
            int t = __shfl_up_sync(0xffffffffu, s, o);
            if (lane >= o) s += t;
        }
        if (lane < 16) wsum[lane] = s;
    }
    __syncthreads();
    int off = (wid > 0) ? wsum[wid - 1] : 0;
    if (i < N_NODES) g_rowptr[i] = off + v - c;
    if (tid == 511) g_blocksums[blockIdx.x] = wsum[15];
}

// merged top-scan + add: each block redundantly prefixes the 256 block sums
__global__ void k_scan_add2() {
    __shared__ int bs[SCAN_BLOCKS];
    __shared__ int pre[SCAN_BLOCKS];
    int tid = threadIdx.x;
    if (tid < SCAN_BLOCKS) bs[tid] = g_blocksums[tid];
    __syncthreads();
    if (tid < SCAN_BLOCKS) {
        int acc = 0;
        for (int j = 0; j < SCAN_BLOCKS; j++) {
            int v = bs[j];
            if (j < tid) acc += v;
        }
        pre[tid] = acc;
    }
    __syncthreads();
    int i = blockIdx.x * 512 + tid;
    if (i < N_NODES) {
        int r = g_rowptr[i] + pre[i >> 9];
        g_rowptr[i] = r;
        g_cursor[i] = r;
    }
    if (i == N_NODES) g_rowptr[N_NODES] = N_EDGES;
}

__global__ void k_fill(const int4* __restrict__ src4, const int4* __restrict__ dst4) {
    int i = blockIdx.x * 256 + threadIdx.x;
    if (i < N_EDGES / 4) {
        int4 s = __ldg(&src4[i]);
        int4 d = __ldg(&dst4[i]);
        int p0 = atomicAdd(&g_cursor[d.x], 1);
        g_col[p0] = s.x; g_wgt[p0] = g_dinv[s.x];
        int p1 = atomicAdd(&g_cursor[d.y], 1);
        g_col[p1] = s.y; g_wgt[p1] = g_dinv[s.y];
        int p2 = atomicAdd(&g_cursor[d.z], 1);
        g_col[p2] = s.z; g_wgt[p2] = g_dinv[s.z];
        int p3 = atomicAdd(&g_cursor[d.w], 1);
        g_col[p3] = s.w; g_wgt[p3] = g_dinv[s.w];
    }
}

// ---------------- prep: split W into bf16 hi/lo, [n][k] orientation ----------------
__global__ void k_prep_w(const float* __restrict__ W1, const float* __restrict__ W2) {
    int i = blockIdx.x * 256 + threadIdx.x;
    if (i < 128 * 128) {
        int k = i >> 7, n = i & 127;
        float v = W1[i];
        __nv_bfloat16 h = __float2bfloat16(v);
        __nv_bfloat16 l = __float2bfloat16(v - __bfloat162float(h));
        g_w1hi[n * 128 + k] = h;
        g_w1lo[n * 128 + k] = l;
    } else if (i < 128 * 128 + 64 * 128) {
        int j = i - 128 * 128;
        int k = j >> 6, n = j & 63;
        float v = W2[j];
        __nv_bfloat16 h = __float2bfloat16(v);
        __nv_bfloat16 l = __float2bfloat16(v - __bfloat162float(h));
        g_w2hi[n * 128 + k] = h;
        g_w2lo[n * 128 + k] = l;
    }
}

// ---------------- bf16 mma.sync helper ----------------
__device__ __forceinline__ void mma_bf16(float& d0, float& d1, float& d2, float& d3,
                                         uint32_t a0, uint32_t a1, uint32_t a2, uint32_t a3,
                                         uint32_t b0, uint32_t b1) {
    asm volatile(
        "mma.sync.aligned.m16n8k16.row.col.f32.bf16.bf16.f32 "
        "{%0,%1,%2,%3}, {%4,%5,%6,%7}, {%8,%9}, {%0,%1,%2,%3};"
        : "+f"(d0), "+f"(d1), "+f"(d2), "+f"(d3)
        : "r"(a0), "r"(a1), "r"(a2), "r"(a3), "r"(b0), "r"(b1));
}
__device__ __forceinline__ uint32_t pack_hi2(float x, float y) {
    __nv_bfloat162 t = __halves2bfloat162(__float2bfloat16(x), __float2bfloat16(y));
    return *(uint32_t*)&t;
}
__device__ __forceinline__ uint32_t pack_lo2(float x, float y) {
    __nv_bfloat16 hx = __float2bfloat16(x), hy = __float2bfloat16(y);
    __nv_bfloat162 t = __halves2bfloat162(__float2bfloat16(x - __bfloat162float(hx)),
                                          __float2bfloat16(y - __bfloat162float(hy)));
    return *(uint32_t*)&t;
}

// ---------------- tensor-core GEMM via mma.sync: O = A @ W (M tile=128, K=128) ----------------
template<int NOUT>
__global__ __launch_bounds__(256) void k_mma_gemm(const float* __restrict__ Ain) {
    extern __shared__ uint32_t smu[];
    constexpr int STR = 68;
    constexpr int WMG = (NOUT == 128) ? 2 : 4;
    constexpr int TM  = 128 / WMG;
    constexpr int MT  = TM / 16;
    constexpr int NT  = 4;

    uint32_t* As_hi = smu;
    uint32_t* As_lo = As_hi + 128 * STR;
    uint32_t* Bs_hi = As_lo + 128 * STR;
    uint32_t* Bs_lo = Bs_hi + NOUT * STR;

    const int tid = threadIdx.x;
    const int wid = tid >> 5;
    const int lane = tid & 31;
    const int g = lane >> 2;
    const int tg = lane & 3;
    const int row0 = blockIdx.x * 128;

    const float* Asrc = (NOUT == 128) ? Ain : g_a1;
    const uint32_t* WhG = (NOUT == 128) ? (const uint32_t*)g_w1hi : (const uint32_t*)g_w2hi;
    const uint32_t* WlG = (NOUT == 128) ? (const uint32_t*)g_w1lo : (const uint32_t*)g_w2lo;

    const float4* A4 = (const float4*)Asrc;
    #pragma unroll 4
    for (int t = 0; t < 16; t++) {
        int i = t * 256 + tid;
        int row = i >> 5, c4 = i & 31;
        int gr = row0 + row;
        float4 v = make_float4(0.f, 0.f, 0.f, 0.f);
        if (gr < N_NODES) v = A4[(size_t)gr * 32 + c4];
        uint32_t h01 = pack_hi2(v.x, v.y), h23 = pack_hi2(v.z, v.w);
        uint32_t l01 = pack_lo2(v.x, v.y), l23 = pack_lo2(v.z, v.w);
        *(uint2*)&As_hi[row * STR + c4 * 2] = make_uint2(h01, h23);
        *(uint2*)&As_lo[row * STR + c4 * 2] = make_uint2(l01, l23);
    }
    for (int i = tid; i < NOUT * 64; i += 256) {
        int n = i >> 6, kp = i & 63;
        Bs_hi[n * STR + kp] = WhG[i];
        Bs_lo[n * STR + kp] = WlG[i];
    }
    __syncthreads();

    const int wm = (NOUT == 128) ? (wid & 1) : (wid & 3);
    const int wn = (NOUT == 128) ? (wid >> 1) : (wid >> 2);

    float d[MT][NT][4];
    #pragma unroll
    for (int mt = 0; mt < MT; mt++)
        #pragma unroll
        for (int nt = 0; nt < NT; nt++)
            #pragma unroll
            for (int j = 0; j < 4; j++) d[mt][nt][j] = 0.f;

    const uint32_t* Aterm[3] = {As_hi, As_hi, As_lo};
    const uint32_t* Bterm[3] = {Bs_hi, Bs_lo, Bs_hi};

    #pragma unroll
    for (int term = 0; term < 3; term++) {
        const uint32_t* Ab = Aterm[term] + (wm * TM + g) * STR;
        const uint32_t* Bb = Bterm[term] + (wn * 32 + g) * STR;
        #pragma unroll
        for (int ks = 0; ks < 8; ks++) {
            int ko = ks * 8 + tg;
            uint32_t a[MT][4], b[NT][2];
            #pragma unroll
            for (int mt = 0; mt < MT; mt++) {
                const uint32_t* Ar = Ab + mt * 16 * STR;
                a[mt][0] = Ar[ko];
                a[mt][1] = Ar[8 * STR + ko];
                a[mt][2] = Ar[ko + 4];
                a[mt][3] = Ar[8 * STR + ko + 4];
            }
            #pragma unroll
            for (int nt = 0; nt < NT; nt++) {
                const uint32_t* Br = Bb + nt * 8 * STR;
                b[nt][0] = Br[ko];
                b[nt][1] = Br[ko + 4];
            }
            #pragma unroll
            for (int mt = 0; mt < MT; mt++)
                #pragma unroll
                for (int nt = 0; nt < NT; nt++)
                    mma_bf16(d[mt][nt][0], d[mt][nt][1], d[mt][nt][2], d[mt][nt][3],
                             a[mt][0], a[mt][1], a[mt][2], a[mt][3],
                             b[nt][0], b[nt][1]);
        }
    }

    #pragma unroll
    for (int mt = 0; mt < MT; mt++) {
        int r0 = row0 + wm * TM + mt * 16 + g;
        #pragma unroll
        for (int nt = 0; nt < NT; nt++) {
            int c = wn * 32 + nt * 8 + tg * 2;
            if (NOUT == 128) {
                if (r0 < N_NODES)
                    *(__half2*)&g_h1h[(size_t)r0 * 128 + c] =
                        __floats2half2_rn(d[mt][nt][0], d[mt][nt][1]);
                if (r0 + 8 < N_NODES)
                    *(__half2*)&g_h1h[(size_t)(r0 + 8) * 128 + c] =
                        __floats2half2_rn(d[mt][nt][2], d[mt][nt][3]);
            } else {
                if (r0 < N_NODES)
                    *(float2*)&g_h2[(size_t)r0 * 64 + c] = make_float2(d[mt][nt][0], d[mt][nt][1]);
                if (r0 + 8 < N_NODES)
                    *(float2*)&g_h2[(size_t)(r0 + 8) * 64 + c] = make_float2(d[mt][nt][2], d[mt][nt][3]);
            }
        }
    }
}

// ---------------- aggregate layer 1 (fp16 gathers, R3-style loop) ----------------
__device__ __forceinline__ void fma_h4(float4& acc, float w, uint2 rv) {
    float2 f0 = __half22float2(*(__half2*)&rv.x);
    float2 f1 = __half22float2(*(__half2*)&rv.y);
    acc.x = fmaf(w, f0.x, acc.x);
    acc.y = fmaf(w, f0.y, acc.y);
    acc.z = fmaf(w, f1.x, acc.z);
    acc.w = fmaf(w, f1.y, acc.w);
}

__global__ __launch_bounds__(256) void k_agg1(const float* __restrict__ b1) {
    int node = blockIdx.x * 8 + (threadIdx.x >> 5);
    if (node >= N_NODES) return;
    int lane = threadIdx.x & 31;
    float di = g_dinv[node];
    const uint2* H = (const uint2*)g_h1h;
    uint2 sv = __ldg(&H[(size_t)node * 32 + lane]);
    float4 acc = make_float4(0.f, 0.f, 0.f, 0.f);
    fma_h4(acc, di, sv);
    int beg = g_rowptr[node];
    int end = g_rowptr[node + 1];
    #pragma unroll 4
    for (int e = beg; e < end; e++) {
        int s = __ldg(&g_col[e]);
        float w = __ldg(&g_wgt[e]);
        uint2 hv = __ldg(&H[(size_t)s * 32 + lane]);
        fma_h4(acc, w, hv);
    }
    float4 bv = ((const float4*)b1)[lane];
    float4 out;
    out.x = fmaxf(fmaf(acc.x, di, bv.x), 0.f);
    out.y = fmaxf(fmaf(acc.y, di, bv.y), 0.f);
    out.z = fmaxf(fmaf(acc.z, di, bv.z), 0.f);
    out.w = fmaxf(fmaf(acc.w, di, bv.w), 0.f);
    ((float4*)g_a1)[(size_t)node * 32 + lane] = out;
}

// ---------------- aggregate layer 2 + bias + log_softmax ----------------
__global__ __launch_bounds__(256) void k_agg2(const float* __restrict__ b2,
                                              float* __restrict__ out) {
    int node = blockIdx.x * 8 + (threadIdx.x >> 5);
    if (node >= N_NODES) return;
    int lane = threadIdx.x & 31;
    float di = g_dinv[node];
    const float2* H = (const float2*)g_h2;
    float2 self = __ldg(&H[(size_t)node * 32 + lane]);
    float2 acc = make_float2(di * self.x, di * self.y);
    int beg = g_rowptr[node];
    int end = g_rowptr[node + 1];
    #pragma unroll 4
    for (int e = beg; e < end; e++) {
        int s = __ldg(&g_col[e]);
        float w = __ldg(&g_wgt[e]);
        float2 hv = __ldg(&H[(size_t)s * 32 + lane]);
        acc.x = fmaf(w, hv.x, acc.x);
        acc.y = fmaf(w, hv.y, acc.y);
    }
    float2 bv = ((const float2*)b2)[lane];
    float vx = fmaf(acc.x, di, bv.x);
    float vy = fmaf(acc.y, di, bv.y);

    float m = fmaxf(vx, vy);
    #pragma unroll
    for (int o = 16; o > 0; o >>= 1) m = fmaxf(m, __shfl_xor_sync(0xffffffffu, m, o));
    float s = expf(vx - m) + expf(vy - m);
    #pragma unroll
    for (int o = 16; o > 0; o >>= 1) s += __shfl_xor_sync(0xffffffffu, s, o);
    float lse = m + logf(s);
    ((float2*)out)[(size_t)node * 32 + lane] = make_float2(vx - lse, vy - lse);
}

// ---------------- launch ----------------
extern "C" void kernel_launch(void* const* d_in, const int* in_sizes, int n_in,
                              void* d_out, int out_size) {
    const float* x  = (const float*)d_in[0];
    const int*   ei = (const int*)d_in[1];
    const float* b1 = (const float*)d_in[3];
    const float* W1 = (const float*)d_in[2];
    const float* W2 = (const float*)d_in[4];
    const float* b2 = (const float*)d_in[5];
    float* out = (float*)d_out;

    const int4* src4 = (const int4*)ei;
    const int4* dst4 = (const int4*)(ei + N_EDGES);

    const int SMEM1 = (2 * 128 * 68 + 2 * 128 * 68) * 4;
    const int SMEM2 = (2 * 128 * 68 + 2 * 64 * 68) * 4;
    cudaFuncSetAttribute(k_mma_gemm<128>, cudaFuncAttributeMaxDynamicSharedMemorySize, SMEM1);
    cudaFuncSetAttribute(k_mma_gemm<64>,  cudaFuncAttributeMaxDynamicSharedMemorySize, SMEM2);

    void* degptr = nullptr;
    cudaGetSymbolAddress(&degptr, g_deg);

    // fork a side stream: weight prep + GEMM1 run concurrently with the CSR build.
    // Stream/events are intentionally NOT destroyed: kernel_launch is invoked only
    // a couple of times host-side (correctness + capture), and destroying objects
    // referenced by an in-progress capture is unsafe.
    cudaStream_t s1;
    cudaStreamCreateWithFlags(&s1, cudaStreamNonBlocking);
    cudaEvent_t evFork, evJoin;
    cudaEventCreateWithFlags(&evFork, cudaEventDisableTiming);
    cudaEventCreateWithFlags(&evJoin, cudaEventDisableTiming);

    cudaEventRecord(evFork, 0);
    cudaStreamWaitEvent(s1, evFork, 0);

    const int NTILES = (N_NODES + 127) / 128;  // 782
    k_prep_w<<<(128 * 128 + 64 * 128 + 255) / 256, 256, 0, s1>>>(W1, W2);
    k_mma_gemm<128><<<NTILES, 256, SMEM1, s1>>>(x);
    cudaEventRecord(evJoin, s1);

    // CSR build on the main (capture) stream
    cudaMemsetAsync(degptr, 0, N_NODES * sizeof(int));
    k_count<<<(N_EDGES / 4 + 255) / 256, 256>>>(dst4);
    k_scan_part<<<SCAN_BLOCKS, 512>>>();
    k_scan_add2<<<(N_NODES + 512) / 512, 512>>>();
    k_fill<<<(N_EDGES / 4 + 255) / 256, 256>>>(src4, dst4);

    cudaStreamWaitEvent(0, evJoin, 0);
    k_agg1<<<(N_NODES + 7) / 8, 256>>>(b1);
    k_mma_gemm<64><<<NTILES, 256, SMEM2>>>(nullptr);
    k_agg2<<<(N_NODES + 7) / 8, 256>>>(b2, out);
}

// round 6
// speedup vs baseline: 1.1218x; 1.0299x over previous
#include <cuda_runtime.h>
#include <cuda_bf16.h>
#include <cuda_fp16.h>
#include <cstdint>
#include <math.h>

#define N_NODES 100000
#define N_EDGES 1600000
#define IN_C 128
#define HID_C 128
#define OUT_C 64
#define SCAN_BLOCKS 256
#define NTILES 782           // ceil(100000/128)
#define CHUNKS 4
#define TILES_PER_CHUNK 196  // 196*128 = 25088 nodes per chunk (last chunk smaller)

// ---------------- scratch (static device globals; no allocation) ----------------
__device__ int   g_deg[N_NODES];
__device__ float g_dinv[N_NODES];
__device__ int   g_rowptr[N_NODES + 1];
__device__ int   g_cursor[N_NODES];
__device__ int2  g_cw[N_EDGES];          // packed (src, wgt-bits)
__device__ int   g_blocksums[SCAN_BLOCKS];
__device__ __align__(16) __half g_h1h[(size_t)N_NODES * HID_C];
__device__ __align__(16) float  g_a1[(size_t)N_NODES * HID_C];
__device__ __align__(16) __half g_h2h[(size_t)N_NODES * OUT_C];
__device__ __align__(16) __nv_bfloat16 g_w1hi[128 * 128];
__device__ __align__(16) __nv_bfloat16 g_w1lo[128 * 128];
__device__ __align__(16) __nv_bfloat16 g_w2hi[64 * 128];
__device__ __align__(16) __nv_bfloat16 g_w2lo[64 * 128];

// ---------------- degree / scan / CSR ----------------
__global__ void k_count(const int4* __restrict__ dst4) {
    int i = blockIdx.x * 256 + threadIdx.x;
    if (i < N_EDGES / 4) {
        int4 d = __ldg(&dst4[i]);
        atomicAdd(&g_deg[d.x], 1);
        atomicAdd(&g_deg[d.y], 1);
        atomicAdd(&g_deg[d.z], 1);
        atomicAdd(&g_deg[d.w], 1);
    }
}

__global__ void k_scan_part() {
    __shared__ int wsum[16];
    int tid = threadIdx.x;
    int lane = tid & 31, wid = tid >> 5;
    int i = blockIdx.x * 512 + tid;
    int c = 0;
    if (i < N_NODES) {
        int d = g_deg[i];
        g_dinv[i] = rsqrtf((float)(d + 1));
        c = d;
    }
    int v = c;
    #pragma unroll
    for (int o = 1; o < 32; o <<= 1) {
        int t = __shfl_up_sync(0xffffffffu, v, o);
        if (lane >= o) v += t;
    }
    if (lane == 31) wsum[wid] = v;
    __syncthreads();
    if (wid == 0) {
        int s = (lane < 16) ? wsum[lane] : 0;
        #pragma unroll
        for (int o = 1; o < 16; o <<= 1) {
            int t = __shfl_up_sync(0xffffffffu, s, o);
            if (lane >= o) s += t;
        }
        if (lane < 16) wsum[lane] = s;
    }
    __syncthreads();
    int off = (wid > 0) ? wsum[wid - 1] : 0;
    if (i < N_NODES) g_rowptr[i] = off + v - c;
    if (tid == 511) g_blocksums[blockIdx.x] = wsum[15];
}

__global__ void k_scan_add2() {
    __shared__ int bs[SCAN_BLOCKS];
    __shared__ int pre[SCAN_BLOCKS];
    int tid = threadIdx.x;
    if (tid < SCAN_BLOCKS) bs[tid] = g_blocksums[tid];
    __syncthreads();
    if (tid < SCAN_BLOCKS) {
        int acc = 0;
        for (int j = 0; j < SCAN_BLOCKS; j++) {
            int v = bs[j];
            if (j < tid) acc += v;
        }
        pre[tid] = acc;
    }
    __syncthreads();
    int i = blockIdx.x * 512 + tid;
    if (i < N_NODES) {
        int r = g_rowptr[i] + pre[i >> 9];
        g_rowptr[i] = r;
        g_cursor[i] = r;
    }
    if (i == N_NODES) g_rowptr[N_NODES] = N_EDGES;
}

__global__ void k_fill(const int4* __restrict__ src4, const int4* __restrict__ dst4) {
    int i = blockIdx.x * 256 + threadIdx.x;
    if (i < N_EDGES / 4) {
        int4 s = __ldg(&src4[i]);
        int4 d = __ldg(&dst4[i]);
        int p0 = atomicAdd(&g_cursor[d.x], 1);
        g_cw[p0] = make_int2(s.x, __float_as_int(g_dinv[s.x]));
        int p1 = atomicAdd(&g_cursor[d.y], 1);
        g_cw[p1] = make_int2(s.y, __float_as_int(g_dinv[s.y]));
        int p2 = atomicAdd(&g_cursor[d.z], 1);
        g_cw[p2] = make_int2(s.z, __float_as_int(g_dinv[s.z]));
        int p3 = atomicAdd(&g_cursor[d.w], 1);
        g_cw[p3] = make_int2(s.w, __float_as_int(g_dinv[s.w]));
    }
}

// ---------------- prep: split W into bf16 hi/lo, [n][k] orientation ----------------
__global__ void k_prep_w(const float* __restrict__ W1, const float* __restrict__ W2) {
    int i = blockIdx.x * 256 + threadIdx.x;
    if (i < 128 * 128) {
        int k = i >> 7, n = i & 127;
        float v = W1[i];
        __nv_bfloat16 h = __float2bfloat16(v);
        __nv_bfloat16 l = __float2bfloat16(v - __bfloat162float(h));
        g_w1hi[n * 128 + k] = h;
        g_w1lo[n * 128 + k] = l;
    } else if (i < 128 * 128 + 64 * 128) {
        int j = i - 128 * 128;
        int k = j >> 6, n = j & 63;
        float v = W2[j];
        __nv_bfloat16 h = __float2bfloat16(v);
        __nv_bfloat16 l = __float2bfloat16(v - __bfloat162float(h));
        g_w2hi[n * 128 + k] = h;
        g_w2lo[n * 128 + k] = l;
    }
}

// ---------------- bf16 mma.sync helper ----------------
__device__ __forceinline__ void mma_bf16(float& d0, float& d1, float& d2, float& d3,
                                         uint32_t a0, uint32_t a1, uint32_t a2, uint32_t a3,
                                         uint32_t b0, uint32_t b1) {
    asm volatile(
        "mma.sync.aligned.m16n8k16.row.col.f32.bf16.bf16.f32 "
        "{%0,%1,%2,%3}, {%4,%5,%6,%7}, {%8,%9}, {%0,%1,%2,%3};"
        : "+f"(d0), "+f"(d1), "+f"(d2), "+f"(d3)
        : "r"(a0), "r"(a1), "r"(a2), "r"(a3), "r"(b0), "r"(b1));
}
__device__ __forceinline__ uint32_t pack_hi2(float x, float y) {
    __nv_bfloat162 t = __halves2bfloat162(__float2bfloat16(x), __float2bfloat16(y));
    return *(uint32_t*)&t;
}
__device__ __forceinline__ uint32_t pack_lo2(float x, float y) {
    __nv_bfloat16 hx = __float2bfloat16(x), hy = __float2bfloat16(y);
    __nv_bfloat162 t = __halves2bfloat162(__float2bfloat16(x - __bfloat162float(hx)),
                                          __float2bfloat16(y - __bfloat162float(hy)));
    return *(uint32_t*)&t;
}

// ---------------- tensor-core GEMM via mma.sync: O = A @ W (M tile=128, K=128) ----------------
template<int NOUT>
__global__ __launch_bounds__(256) void k_mma_gemm(const float* __restrict__ Ain, int tile0) {
    extern __shared__ uint32_t smu[];
    constexpr int STR = 68;
    constexpr int WMG = (NOUT == 128) ? 2 : 4;
    constexpr int TM  = 128 / WMG;
    constexpr int MT  = TM / 16;
    constexpr int NT  = 4;

    uint32_t* As_hi = smu;
    uint32_t* As_lo = As_hi + 128 * STR;
    uint32_t* Bs_hi = As_lo + 128 * STR;
    uint32_t* Bs_lo = Bs_hi + NOUT * STR;

    const int tid = threadIdx.x;
    const int wid = tid >> 5;
    const int lane = tid & 31;
    const int g = lane >> 2;
    const int tg = lane & 3;
    const int row0 = (tile0 + blockIdx.x) * 128;

    const float* Asrc = (NOUT == 128) ? Ain : g_a1;
    const uint32_t* WhG = (NOUT == 128) ? (const uint32_t*)g_w1hi : (const uint32_t*)g_w2hi;
    const uint32_t* WlG = (NOUT == 128) ? (const uint32_t*)g_w1lo : (const uint32_t*)g_w2lo;

    const float4* A4 = (const float4*)Asrc;
    #pragma unroll 4
    for (int t = 0; t < 16; t++) {
        int i = t * 256 + tid;
        int row = i >> 5, c4 = i & 31;
        int gr = row0 + row;
        float4 v = make_float4(0.f, 0.f, 0.f, 0.f);
        if (gr < N_NODES) v = A4[(size_t)gr * 32 + c4];
        uint32_t h01 = pack_hi2(v.x, v.y), h23 = pack_hi2(v.z, v.w);
        uint32_t l01 = pack_lo2(v.x, v.y), l23 = pack_lo2(v.z, v.w);
        *(uint2*)&As_hi[row * STR + c4 * 2] = make_uint2(h01, h23);
        *(uint2*)&As_lo[row * STR + c4 * 2] = make_uint2(l01, l23);
    }
    for (int i = tid; i < NOUT * 64; i += 256) {
        int n = i >> 6, kp = i & 63;
        Bs_hi[n * STR + kp] = WhG[i];
        Bs_lo[n * STR + kp] = WlG[i];
    }
    __syncthreads();

    const int wm = (NOUT == 128) ? (wid & 1) : (wid & 3);
    const int wn = (NOUT == 128) ? (wid >> 1) : (wid >> 2);

    float d[MT][NT][4];
    #pragma unroll
    for (int mt = 0; mt < MT; mt++)
        #pragma unroll
        for (int nt = 0; nt < NT; nt++)
            #pragma unroll
            for (int j = 0; j < 4; j++) d[mt][nt][j] = 0.f;

    const uint32_t* Aterm[3] = {As_hi, As_hi, As_lo};
    const uint32_t* Bterm[3] = {Bs_hi, Bs_lo, Bs_hi};

    #pragma unroll
    for (int term = 0; term < 3; term++) {
        const uint32_t* Ab = Aterm[term] + (wm * TM + g) * STR;
        const uint32_t* Bb = Bterm[term] + (wn * 32 + g) * STR;
        #pragma unroll
        for (int ks = 0; ks < 8; ks++) {
            int ko = ks * 8 + tg;
            uint32_t a[MT][4], b[NT][2];
            #pragma unroll
            for (int mt = 0; mt < MT; mt++) {
                const uint32_t* Ar = Ab + mt * 16 * STR;
                a[mt][0] = Ar[ko];
                a[mt][1] = Ar[8 * STR + ko];
                a[mt][2] = Ar[ko + 4];
                a[mt][3] = Ar[8 * STR + ko + 4];
            }
            #pragma unroll
            for (int nt = 0; nt < NT; nt++) {
                const uint32_t* Br = Bb + nt * 8 * STR;
                b[nt][0] = Br[ko];
                b[nt][1] = Br[ko + 4];
            }
            #pragma unroll
            for (int mt = 0; mt < MT; mt++)
                #pragma unroll
                for (int nt = 0; nt < NT; nt++)
                    mma_bf16(d[mt][nt][0], d[mt][nt][1], d[mt][nt][2], d[mt][nt][3],
                             a[mt][0], a[mt][1], a[mt][2], a[mt][3],
                             b[nt][0], b[nt][1]);
        }
    }

    #pragma unroll
    for (int mt = 0; mt < MT; mt++) {
        int r0 = row0 + wm * TM + mt * 16 + g;
        #pragma unroll
        for (int nt = 0; nt < NT; nt++) {
            int c = wn * 32 + nt * 8 + tg * 2;
            if (NOUT == 128) {
                if (r0 < N_NODES)
                    *(__half2*)&g_h1h[(size_t)r0 * 128 + c] =
                        __floats2half2_rn(d[mt][nt][0], d[mt][nt][1]);
                if (r0 + 8 < N_NODES)
                    *(__half2*)&g_h1h[(size_t)(r0 + 8) * 128 + c] =
                        __floats2half2_rn(d[mt][nt][2], d[mt][nt][3]);
            } else {
                if (r0 < N_NODES)
                    *(__half2*)&g_h2h[(size_t)r0 * 64 + c] =
                        __floats2half2_rn(d[mt][nt][0], d[mt][nt][1]);
                if (r0 + 8 < N_NODES)
                    *(__half2*)&g_h2h[(size_t)(r0 + 8) * 64 + c] =
                        __floats2half2_rn(d[mt][nt][2], d[mt][nt][3]);
            }
        }
    }
}

// ---------------- aggregate layer 1 (fp16 gathers) + bias + relu ----------------
__device__ __forceinline__ void fma_h4(float4& acc, float w, uint2 rv) {
    float2 f0 = __half22float2(*(__half2*)&rv.x);
    float2 f1 = __half22float2(*(__half2*)&rv.y);
    acc.x = fmaf(w, f0.x, acc.x);
    acc.y = fmaf(w, f0.y, acc.y);
    acc.z = fmaf(w, f1.x, acc.z);
    acc.w = fmaf(w, f1.y, acc.w);
}

__global__ __launch_bounds__(256) void k_agg1(const float* __restrict__ b1,
                                              int node0, int node1) {
    int node = node0 + blockIdx.x * 8 + (threadIdx.x >> 5);
    if (node >= node1) return;
    int lane = threadIdx.x & 31;
    float di = g_dinv[node];
    const uint2* H = (const uint2*)g_h1h;
    uint2 sv = __ldg(&H[(size_t)node * 32 + lane]);
    float4 acc = make_float4(0.f, 0.f, 0.f, 0.f);
    fma_h4(acc, di, sv);
    int beg = g_rowptr[node];
    int end = g_rowptr[node + 1];
    #pragma unroll 4
    for (int e = beg; e < end; e++) {
        int2 cw = __ldg(&g_cw[e]);
        float w = __int_as_float(cw.y);
        uint2 hv = __ldg(&H[(size_t)cw.x * 32 + lane]);
        fma_h4(acc, w, hv);
    }
    float4 bv = ((const float4*)b1)[lane];
    float4 out;
    out.x = fmaxf(fmaf(acc.x, di, bv.x), 0.f);
    out.y = fmaxf(fmaf(acc.y, di, bv.y), 0.f);
    out.z = fmaxf(fmaf(acc.z, di, bv.z), 0.f);
    out.w = fmaxf(fmaf(acc.w, di, bv.w), 0.f);
    ((float4*)g_a1)[(size_t)node * 32 + lane] = out;
}

// ---------------- aggregate layer 2 (fp16 gathers) + bias + log_softmax ----------------
__global__ __launch_bounds__(256) void k_agg2(const float* __restrict__ b2,
                                              float* __restrict__ out) {
    int node = blockIdx.x * 8 + (threadIdx.x >> 5);
    if (node >= N_NODES) return;
    int lane = threadIdx.x & 31;
    float di = g_dinv[node];
    const __half2* H = (const __half2*)g_h2h;  // row = 32 half2
    float2 self = __half22float2(__ldg(&H[(size_t)node * 32 + lane]));
    float2 acc = make_float2(di * self.x, di * self.y);
    int beg = g_rowptr[node];
    int end = g_rowptr[node + 1];
    #pragma unroll 4
    for (int e = beg; e < end; e++) {
        int2 cw = __ldg(&g_cw[e]);
        float w = __int_as_float(cw.y);
        float2 hv = __half22float2(__ldg(&H[(size_t)cw.x * 32 + lane]));
        acc.x = fmaf(w, hv.x, acc.x);
        acc.y = fmaf(w, hv.y, acc.y);
    }
    float2 bv = ((const float2*)b2)[lane];
    float vx = fmaf(acc.x, di, bv.x);
    float vy = fmaf(acc.y, di, bv.y);

    float m = fmaxf(vx, vy);
    #pragma unroll
    for (int o = 16; o > 0; o >>= 1) m = fmaxf(m, __shfl_xor_sync(0xffffffffu, m, o));
    float s = expf(vx - m) + expf(vy - m);
    #pragma unroll
    for (int o = 16; o > 0; o >>= 1) s += __shfl_xor_sync(0xffffffffu, s, o);
    float lse = m + logf(s);
    ((float2*)out)[(size_t)node * 32 + lane] = make_float2(vx - lse, vy - lse);
}

// ---------------- launch ----------------
extern "C" void kernel_launch(void* const* d_in, const int* in_sizes, int n_in,
                              void* d_out, int out_size) {
    const float* x  = (const float*)d_in[0];
    const int*   ei = (const int*)d_in[1];
    const float* W1 = (const float*)d_in[2];
    const float* b1 = (const float*)d_in[3];
    const float* W2 = (const float*)d_in[4];
    const float* b2 = (const float*)d_in[5];
    float* out = (float*)d_out;

    const int4* src4 = (const int4*)ei;
    const int4* dst4 = (const int4*)(ei + N_EDGES);

    const int SMEM1 = (2 * 128 * 68 + 2 * 128 * 68) * 4;
    const int SMEM2 = (2 * 128 * 68 + 2 * 64 * 68) * 4;
    cudaFuncSetAttribute(k_mma_gemm<128>, cudaFuncAttributeMaxDynamicSharedMemorySize, SMEM1);
    cudaFuncSetAttribute(k_mma_gemm<64>,  cudaFuncAttributeMaxDynamicSharedMemorySize, SMEM2);

    void* degptr = nullptr;
    cudaGetSymbolAddress(&degptr, g_deg);

    // side stream + events (created per call; capture-safe, no device allocation)
    cudaStream_t s1;
    cudaStreamCreateWithFlags(&s1, cudaStreamNonBlocking);
    cudaEvent_t evFork, evG1, evG2;
    cudaEvent_t evA[CHUNKS];
    cudaEventCreateWithFlags(&evFork, cudaEventDisableTiming);
    cudaEventCreateWithFlags(&evG1, cudaEventDisableTiming);
    cudaEventCreateWithFlags(&evG2, cudaEventDisableTiming);
    for (int c = 0; c < CHUNKS; c++) cudaEventCreateWithFlags(&evA[c], cudaEventDisableTiming);

    cudaEventRecord(evFork, 0);
    cudaStreamWaitEvent(s1, evFork, 0);

    // side stream: weight prep + GEMM1 (independent of graph structure)
    k_prep_w<<<(128 * 128 + 64 * 128 + 255) / 256, 256, 0, s1>>>(W1, W2);
    k_mma_gemm<128><<<NTILES, 256, SMEM1, s1>>>(x, 0);
    cudaEventRecord(evG1, s1);

    // main stream: CSR build
    cudaMemsetAsync(degptr, 0, N_NODES * sizeof(int));
    k_count<<<(N_EDGES / 4 + 255) / 256, 256>>>(dst4);
    k_scan_part<<<SCAN_BLOCKS, 512>>>();
    k_scan_add2<<<(N_NODES + 512) / 512, 512>>>();
    k_fill<<<(N_EDGES / 4 + 255) / 256, 256>>>(src4, dst4);

    cudaStreamWaitEvent(0, evG1, 0);

    // pipelined agg1 (main) -> gemm2 chunk (side)
    for (int c = 0; c < CHUNKS; c++) {
        int t0 = c * TILES_PER_CHUNK;
        int t1 = (c == CHUNKS - 1) ? NTILES : (c + 1) * TILES_PER_CHUNK;
        int n0 = t0 * 128;
        int n1 = (t1 * 128 < N_NODES) ? t1 * 128 : N_NODES;
        int blocks = (n1 - n0 + 7) / 8;
        k_agg1<<<blocks, 256>>>(b1, n0, n1);
        cudaEventRecord(evA[c], 0);
        cudaStreamWaitEvent(s1, evA[c], 0);
        k_mma_gemm<64><<<t1 - t0, 256, SMEM2, s1>>>(nullptr, t0);
    }
    cudaEventRecord(evG2, s1);
    cudaStreamWaitEvent(0, evG2, 0);

    k_agg2<<<(N_NODES + 7) / 8, 256>>>(b2, out);
}